// round 1
// baseline (speedup 1.0000x reference)
#include <cuda_runtime.h>
#include <math.h>

// GAT_28295244546247 — analytic collapse:
//   softmax_j(s_i[i] + s_j[j] + b) == softmax_j(s_j[j])  (row constant cancels)
//   => attention output rows are IDENTICAL across i for both layers.
//   Layer1: out_row = mean_h( W1 @ (sum_j p[h,j] x_j) + b1 ), p = softmax(s_j)
//   Layer2: input rows identical -> uniform softmax -> out_row = leaky_relu(W2@out1+b2)
//   a2_w / a2_b provably do not affect the output.

#define N_NODES 4096
#define F_IN    64
#define F_HID   64
#define F_OUT   32
#define NH      8
#define JCHUNK  128
#define NBLK    (N_NODES / JCHUNK)   // 32

__device__ float g_Zpart[NBLK * NH];
__device__ float g_qpart[NBLK * NH * F_IN];
__device__ float g_final[F_OUT];

// K1: per 128-row chunk of x: scores -> exp -> partial Z[h], partial q[h][f]
__global__ __launch_bounds__(256) void gat_k1(const float* __restrict__ x,
                                              const float* __restrict__ W1,
                                              const float* __restrict__ b1,
                                              const float* __restrict__ a1w,
                                              const float* __restrict__ a1b) {
    __shared__ float xs[JCHUNK * 65];    // padded stride 65: conflict-free row reads
    __shared__ float us[NH * F_IN];      // u[h][k] = sum_f a1w[h,64+f] * W1[f,k]
    __shared__ float cs[NH];             // c[h]    = sum_f a1w[h,64+f] * b1[f] + a1b[h]
    __shared__ float es[JCHUNK * NH];    // exp(score)
    __shared__ float zs[NH];
    __shared__ float qs[NH * F_IN];

    const int t  = threadIdx.x;
    const int b  = blockIdx.x;
    const int j0 = b * JCHUNK;

    // stage x chunk (coalesced float4 loads, scalar padded stores)
    const float4* xg = (const float4*)(x + j0 * F_IN);
    for (int idx = t; idx < JCHUNK * F_IN / 4; idx += 256) {
        float4 v = xg[idx];
        int jj = idx >> 4;
        int kk = (idx & 15) << 2;
        float* dst = &xs[jj * 65 + kk];
        dst[0] = v.x; dst[1] = v.y; dst[2] = v.z; dst[3] = v.w;
    }
    // fold a1_w (j-half) through W1  (redundant per block; 32K MACs, trivial)
    for (int e = t; e < NH * F_IN; e += 256) {
        int h = e >> 6, k = e & 63;
        float s = 0.f;
        #pragma unroll 8
        for (int f = 0; f < F_HID; f++)
            s += a1w[h * 2 * F_HID + F_HID + f] * W1[f * F_IN + k];
        us[e] = s;
    }
    if (t < NH) {
        float s = a1b[t];
        #pragma unroll 8
        for (int f = 0; f < F_HID; f++)
            s += a1w[t * 2 * F_HID + F_HID + f] * b1[f];
        cs[t] = s;
    }
    for (int e = t; e < NH * F_IN; e += 256) qs[e] = 0.f;
    __syncthreads();

    // scores + exp (one row per thread; |s| <~ 4, exp safe without max-shift)
    if (t < JCHUNK) {
        float s[NH];
        #pragma unroll
        for (int h = 0; h < NH; h++) s[h] = cs[h];
        #pragma unroll 4
        for (int k = 0; k < F_IN; k++) {
            float xv = xs[t * 65 + k];
            #pragma unroll
            for (int h = 0; h < NH; h++) s[h] += us[h * F_IN + k] * xv;
        }
        #pragma unroll
        for (int h = 0; h < NH; h++) es[t * NH + h] = expf(s[h]);
    }
    __syncthreads();

    // partial Z
    if (t < NH) {
        float z = 0.f;
        for (int j = 0; j < JCHUNK; j++) z += es[j * NH + t];
        zs[t] = z;
    }
    // partial q[h][f] = sum_j e[j,h] * x[j,f]   (f-parallel, 4 j-lanes)
    {
        const int f = t & 63, l = t >> 6;
        float acc[NH];
        #pragma unroll
        for (int h = 0; h < NH; h++) acc[h] = 0.f;
        for (int j = l; j < JCHUNK; j += 4) {
            float xv = xs[j * 65 + f];
            #pragma unroll
            for (int h = 0; h < NH; h++) acc[h] += es[j * NH + h] * xv;
        }
        #pragma unroll
        for (int h = 0; h < NH; h++) atomicAdd(&qs[h * F_IN + f], acc[h]);
    }
    __syncthreads();

    for (int e = t; e < NH * F_IN; e += 256)
        g_qpart[b * NH * F_IN + e] = qs[e];
    if (t < NH) g_Zpart[b * NH + t] = zs[t];
}

// K2: combine partials, finish both layers analytically -> final[32]
__global__ __launch_bounds__(256) void gat_k2(const float* __restrict__ W1,
                                              const float* __restrict__ b1,
                                              const float* __restrict__ W2,
                                              const float* __restrict__ b2) {
    __shared__ float qn[NH * F_IN];
    __shared__ float Z[NH];
    __shared__ float vs[NH * F_HID];
    __shared__ float os[F_HID];
    const int t = threadIdx.x;

    if (t < NH) {
        float z = 0.f;
        for (int b = 0; b < NBLK; b++) z += g_Zpart[b * NH + t];
        Z[t] = z;
    }
    __syncthreads();
    for (int e = t; e < NH * F_IN; e += 256) {
        float s = 0.f;
        for (int b = 0; b < NBLK; b++) s += g_qpart[b * NH * F_IN + e];
        qn[e] = s / Z[e >> 6];
    }
    __syncthreads();
    // v[h][f] = b1[f] + W1[f,:] . qn[h,:]
    for (int e = t; e < NH * F_HID; e += 256) {
        int h = e >> 6, f = e & 63;
        float s = b1[f];
        #pragma unroll 8
        for (int k = 0; k < F_IN; k++)
            s += W1[f * F_IN + k] * qn[h * F_IN + k];
        vs[e] = s;
    }
    __syncthreads();
    // mean over heads -> leaky_relu -> elu
    if (t < F_HID) {
        float m = 0.f;
        #pragma unroll
        for (int h = 0; h < NH; h++) m += vs[h * F_HID + t];
        m *= (1.0f / NH);
        float lr = m > 0.f ? m : 0.2f * m;
        os[t] = lr > 0.f ? lr : expm1f(lr);
    }
    __syncthreads();
    // layer 2: uniform attention => row = leaky_relu(W2 @ os + b2)
    if (t < F_OUT) {
        float s = b2[t];
        #pragma unroll 8
        for (int f = 0; f < F_HID; f++)
            s += W2[t * F_HID + f] * os[f];
        g_final[t] = s > 0.f ? s : 0.2f * s;
    }
}

// K3: broadcast final[32] to out[4096][32] with float4 stores
__global__ __launch_bounds__(256) void gat_k3(float* __restrict__ out) {
    __shared__ float fs[F_OUT];
    const int t = threadIdx.x;
    if (t < F_OUT) fs[t] = g_final[t];
    __syncthreads();
    int idx = blockIdx.x * blockDim.x + t;         // one float4 per thread
    int f0 = (idx * 4) & (F_OUT - 1);
    float4 v;
    v.x = fs[f0]; v.y = fs[f0 + 1]; v.z = fs[f0 + 2]; v.w = fs[f0 + 3];
    ((float4*)out)[idx] = v;
}

extern "C" void kernel_launch(void* const* d_in, const int* in_sizes, int n_in,
                              void* d_out, int out_size) {
    const float* x   = (const float*)d_in[0];
    const float* W1  = (const float*)d_in[1];
    const float* b1  = (const float*)d_in[2];
    const float* a1w = (const float*)d_in[3];
    const float* a1b = (const float*)d_in[4];
    const float* W2  = (const float*)d_in[5];
    const float* b2  = (const float*)d_in[6];
    // d_in[7] (a2_w), d_in[8] (a2_b) provably cannot affect the output.

    gat_k1<<<NBLK, 256>>>(x, W1, b1, a1w, a1b);
    gat_k2<<<1, 256>>>(W1, b1, W2, b2);
    gat_k3<<<(N_NODES * F_OUT / 4) / 256, 256>>>((float*)d_out);
}

// round 2
// speedup vs baseline: 1.5348x; 1.5348x over previous
#include <cuda_runtime.h>

// GAT_28295244546247 — fully fused single kernel.
// Analytic collapse (proved in R0/R1): softmax row-constant cancels =>
//   out_row identical for all i; layer2 softmax exactly uniform;
//   a2_w / a2_b cannot affect the output.
// Grid = 128 blocks (all co-resident on 148 SMs) with last-block finalize +
// flag spin for the global sync; state self-resets for graph replay.

#define N_NODES 4096
#define F_IN    64
#define F_OUT   32
#define NH      8
#define NBLK    128
#define RPB     32           // rows per block
#define NT      256

__device__ float4 g_qpart4[NBLK * 128];        // per-block partial q [blk][8h*64f]
__device__ float  g_Zpart[NBLK * NH];
__device__ volatile float g_final[F_OUT];
__device__ unsigned g_arrive = 0;
__device__ volatile int g_done = 0;
__device__ unsigned g_exit = 0;

__global__ __launch_bounds__(NT) void gat_fused(
    const float* __restrict__ x,   const float* __restrict__ W1,
    const float* __restrict__ b1,  const float* __restrict__ a1w,
    const float* __restrict__ a1b, const float* __restrict__ W2,
    const float* __restrict__ b2,  float* __restrict__ out)
{
    __shared__ float W1s[64 * 65];                 // padded: conflict-free both axes
    __shared__ __align__(16) float a1wjs[NH * 64]; // a1w[:,64:128]
    __shared__ float b1s[64];
    __shared__ __align__(16) float us[NH * 64];    // folded u; reused as qn in tail
    __shared__ float cs[NH];
    __shared__ float xs[RPB * 65];
    __shared__ float es[RPB * NH];                 // exp(scores)
    __shared__ float qs[NH * 64];
    __shared__ float zs[NH];
    __shared__ float os[64];
    __shared__ float fs[F_OUT];
    __shared__ int   s_last;

    const int t = threadIdx.x;
    const int b = blockIdx.x;

    // ---- stage weights into smem (coalesced float4) ----
    {
        const float4* w4 = (const float4*)W1;
        for (int i = t; i < 1024; i += NT) {
            float4 v = w4[i];
            int f = i >> 4, k = (i & 15) << 2;
            float* d = &W1s[f * 65 + k];
            d[0] = v.x; d[1] = v.y; d[2] = v.z; d[3] = v.w;
        }
        const float4* a4 = (const float4*)a1w;     // [8][32] float4 rows
        if (t < 128) {
            int h = t >> 4, q = t & 15;
            ((float4*)a1wjs)[h * 16 + q] = a4[h * 32 + 16 + q];  // j-half
        }
        if (t < 16) ((float4*)b1s)[t] = ((const float4*)b1)[t];
        for (int e = t; e < NH * 64; e += NT) qs[e] = 0.f;
    }
    __syncthreads();

    // ---- fold: u[h][k] = sum_f a1wj[h][f] * W1[f][k];  c[h] = a1b + a1wj.b1 ----
    for (int e = t; e < NH * 64; e += NT) {
        int h = e >> 6, k = e & 63;
        const float* ar = &a1wjs[h * 64];
        float s = 0.f;
        #pragma unroll 16
        for (int f = 0; f < 64; f++) s += ar[f] * W1s[f * 65 + k];
        us[e] = s;
    }
    if (t < NH) {
        float s = a1b[t];
        #pragma unroll 16
        for (int f = 0; f < 64; f++) s += a1wjs[t * 64 + f] * b1s[f];
        cs[t] = s;
    }
    __syncthreads();

    // ---- scores: 8 threads per row, 32 rows, exp ----
    {
        const int g = t >> 3, u = t & 7;
        const int j = b * RPB + g;
        const float4* xr = (const float4*)(x + j * 64 + u * 8);
        float4 x0 = xr[0], x1 = xr[1];
        float* xd = &xs[g * 65 + u * 8];
        xd[0] = x0.x; xd[1] = x0.y; xd[2] = x0.z; xd[3] = x0.w;
        xd[4] = x1.x; xd[5] = x1.y; xd[6] = x1.z; xd[7] = x1.w;
        float s[NH];
        #pragma unroll
        for (int h = 0; h < NH; h++) {
            float4 u0 = ((const float4*)us)[h * 16 + u * 2];
            float4 u1 = ((const float4*)us)[h * 16 + u * 2 + 1];
            s[h] = u0.x * x0.x + u0.y * x0.y + u0.z * x0.z + u0.w * x0.w
                 + u1.x * x1.x + u1.y * x1.y + u1.z * x1.z + u1.w * x1.w;
        }
        #pragma unroll
        for (int o = 1; o < 8; o <<= 1) {
            #pragma unroll
            for (int h = 0; h < NH; h++)
                s[h] += __shfl_xor_sync(0xffffffffu, s[h], o);
        }
        float sv = s[0];                      // select own head without spills
        #pragma unroll
        for (int h = 1; h < NH; h++) sv = (u == h) ? s[h] : sv;
        es[t] = __expf(sv + cs[u]);           // es[g*8+u]
    }
    __syncthreads();

    // ---- partial q[h][f] = sum_j e[j,h] * x[j,f]  (f-parallel, 4 j-lanes) ----
    {
        const int f = t & 63, l = t >> 6;
        float acc[NH];
        #pragma unroll
        for (int h = 0; h < NH; h++) acc[h] = 0.f;
        for (int jj = l; jj < RPB; jj += 4) {
            float xv = xs[jj * 65 + f];
            #pragma unroll
            for (int h = 0; h < NH; h++) acc[h] += es[jj * 8 + h] * xv;  // broadcast LDS
        }
        #pragma unroll
        for (int h = 0; h < NH; h++) atomicAdd(&qs[h * 64 + f], acc[h]);
    }
    __syncthreads();

    // ---- publish partials ----
    {
        float* gq = (float*)g_qpart4 + b * 512;
        for (int e = t; e < 512; e += NT) gq[e] = qs[e];
        if (t < NH) {
            float z = 0.f;
            #pragma unroll
            for (int jj = 0; jj < RPB; jj++) z += es[jj * 8 + t];
            g_Zpart[b * NH + t] = z;
        }
    }
    __threadfence();
    __syncthreads();
    if (t == 0) s_last = (atomicAdd(&g_arrive, 1) == NBLK - 1);
    __syncthreads();

    if (s_last) {
        __threadfence();
        // reduce 128 partials (float4) into us (reused as qn)
        if (t < 128) {
            float4 a = make_float4(0.f, 0.f, 0.f, 0.f);
            #pragma unroll 8
            for (int blk = 0; blk < NBLK; blk++) {
                float4 v = g_qpart4[blk * 128 + t];
                a.x += v.x; a.y += v.y; a.z += v.z; a.w += v.w;
            }
            ((float4*)us)[t] = a;
        }
        if (t >= 128 && t < 128 + NH) {
            int h = t - 128;
            float z = 0.f;
            #pragma unroll 8
            for (int blk = 0; blk < NBLK; blk++) z += g_Zpart[blk * NH + h];
            zs[h] = z;
        }
        __syncthreads();
        for (int e = t; e < 512; e += NT) us[e] /= zs[e >> 6];
        __syncthreads();
        // out1_row = elu(leaky_relu(mean_h(W1 @ qn[h] + b1)))
        if (t < 64) {
            float m = 0.f;
            #pragma unroll
            for (int h = 0; h < NH; h++) {
                float s = b1s[t];
                #pragma unroll 16
                for (int k = 0; k < 64; k++) s += W1s[t * 65 + k] * us[h * 64 + k];
                m += s;
            }
            m *= (1.f / NH);
            float lr = m > 0.f ? m : 0.2f * m;
            os[t] = lr > 0.f ? lr : (__expf(lr) - 1.f);
        }
        __syncthreads();
        // layer2 (uniform attention): final = leaky_relu(W2 @ os + b2)
        if (t < F_OUT) {
            float s = b2[t];
            #pragma unroll 16
            for (int f = 0; f < 64; f++) s += W2[t * 64 + f] * os[f];
            float r = s > 0.f ? s : 0.2f * s;
            fs[t] = r;
            g_final[t] = r;
            __threadfence();
        }
        __syncthreads();
        if (t == 0) g_done = 1;
    } else {
        if (t == 0) { while (g_done == 0) __nanosleep(64); }
        __syncthreads();
        __threadfence();
        if (t < F_OUT) fs[t] = g_final[t];
        __syncthreads();
    }

    // ---- broadcast final row to this block's 32 output rows (float4) ----
    {
        int f0 = (t & 7) << 2;
        float4 v = make_float4(fs[f0], fs[f0 + 1], fs[f0 + 2], fs[f0 + 3]);
        ((float4*)out)[b * 256 + t] = v;
    }

    // ---- reset state for next graph replay (last exiter) ----
    __syncthreads();
    if (t == 0) {
        if (atomicAdd(&g_exit, 1) == NBLK - 1) {
            g_arrive = 0; g_exit = 0; g_done = 0;
        }
    }
}

extern "C" void kernel_launch(void* const* d_in, const int* in_sizes, int n_in,
                              void* d_out, int out_size) {
    const float* x   = (const float*)d_in[0];
    const float* W1  = (const float*)d_in[1];
    const float* b1  = (const float*)d_in[2];
    const float* a1w = (const float*)d_in[3];
    const float* a1b = (const float*)d_in[4];
    const float* W2  = (const float*)d_in[5];
    const float* b2  = (const float*)d_in[6];
    // d_in[7] (a2_w), d_in[8] (a2_b): provably no effect on output.

    gat_fused<<<NBLK, NT>>>(x, W1, b1, a1w, a1b, W2, b2, (float*)d_out);
}

// round 3
// speedup vs baseline: 2.2692x; 1.4785x over previous
#include <cuda_runtime.h>

// GAT_28295244546247 — fused single kernel, v3.
// Analytic collapse (R0): softmax row-constant cancels => identical output rows,
// layer2 softmax exactly uniform, a2_w/a2_b have no effect.
// v3: RED-atomic global accumulation + redundant tail on all blocks
//     (one grid sync point, no single-block finalize, no wake broadcast).

#define F_OUT 32
#define NH    8
#define NBLK  128
#define RPB   32
#define NT    256

__device__ float    g_q[NH * 64];   // RED accumulators (zeroed at init / by last exiter)
__device__ float    g_Z[NH];
__device__ unsigned g_arrive = 0;
__device__ unsigned g_exit   = 0;

__global__ __launch_bounds__(NT) void gat_fused(
    const float* __restrict__ x,   const float* __restrict__ W1,
    const float* __restrict__ b1,  const float* __restrict__ a1w,
    const float* __restrict__ a1b, const float* __restrict__ W2,
    const float* __restrict__ b2,  float* __restrict__ out)
{
    __shared__ float W1s[64 * 65];                  // padded both-axis conflict-free
    __shared__ __align__(16) float W2s[F_OUT * 64];
    __shared__ __align__(16) float a1wjs[NH * 64];  // a1w[:,64:128]
    __shared__ __align__(16) float b1s[64];
    __shared__ __align__(16) float b2s[F_OUT];
    __shared__ __align__(16) float us[NH * 64];     // folded u; reused as qn in tail
    __shared__ float cs[NH];
    __shared__ float xs[RPB * 65];
    __shared__ float es[RPB * NH];
    __shared__ float qs[NH * 64];                   // block q-partial; reused as vs in tail
    __shared__ float zs[NH];
    __shared__ float os[64];
    __shared__ float fs[F_OUT];
    __shared__ int   s_last;

    const int t = threadIdx.x;
    const int b = blockIdx.x;
    const int g = t >> 3, u = t & 7;

    // ---- issue x loads FIRST (latency overlaps weight staging + fold) ----
    const float4* xr = (const float4*)(x + (b * RPB + g) * 64 + u * 8);
    float4 x0 = xr[0], x1 = xr[1];

    // ---- stage all weights into smem (coalesced float4) ----
    {
        const float4* w4 = (const float4*)W1;
        for (int i = t; i < 1024; i += NT) {
            float4 v = w4[i];
            int f = i >> 4, k = (i & 15) << 2;
            float* d = &W1s[f * 65 + k];
            d[0] = v.x; d[1] = v.y; d[2] = v.z; d[3] = v.w;
        }
        for (int i = t; i < 512; i += NT)
            ((float4*)W2s)[i] = ((const float4*)W2)[i];
        if (t < 128) {
            int h = t >> 4, q = t & 15;
            ((float4*)a1wjs)[h * 16 + q] = ((const float4*)a1w)[h * 32 + 16 + q];
        }
        if (t < 16)               ((float4*)b1s)[t]      = ((const float4*)b1)[t];
        else if (t < 24)          ((float4*)b2s)[t - 16] = ((const float4*)b2)[t - 16];
        for (int e = t; e < NH * 64; e += NT) qs[e] = 0.f;
    }
    // park x in smem for the q-accumulation phase
    {
        float* xd = &xs[g * 65 + u * 8];
        xd[0] = x0.x; xd[1] = x0.y; xd[2] = x0.z; xd[3] = x0.w;
        xd[4] = x1.x; xd[5] = x1.y; xd[6] = x1.z; xd[7] = x1.w;
    }
    __syncthreads();

    // ---- fold: u[h][k] = a1wj[h] . W1[:,k];  c[h] = a1b[h] + a1wj[h] . b1 ----
    for (int e = t; e < NH * 64; e += NT) {
        int h = e >> 6, k = e & 63;
        const float* ar = &a1wjs[h * 64];
        float s = 0.f;
        #pragma unroll 16
        for (int f = 0; f < 64; f++) s += ar[f] * W1s[f * 65 + k];
        us[e] = s;
    }
    if (t < NH) {
        float s = a1b[t];
        #pragma unroll 16
        for (int f = 0; f < 64; f++) s += a1wjs[t * 64 + f] * b1s[f];
        cs[t] = s;
    }
    __syncthreads();

    // ---- scores: 8 threads/row on register-resident x, shfl reduce, exp ----
    {
        float s[NH];
        #pragma unroll
        for (int h = 0; h < NH; h++) {
            float4 u0 = ((const float4*)us)[h * 16 + u * 2];
            float4 u1 = ((const float4*)us)[h * 16 + u * 2 + 1];
            s[h] = u0.x * x0.x + u0.y * x0.y + u0.z * x0.z + u0.w * x0.w
                 + u1.x * x1.x + u1.y * x1.y + u1.z * x1.z + u1.w * x1.w;
        }
        #pragma unroll
        for (int o = 1; o < 8; o <<= 1) {
            #pragma unroll
            for (int h = 0; h < NH; h++)
                s[h] += __shfl_xor_sync(0xffffffffu, s[h], o);
        }
        float sv = s[0];
        #pragma unroll
        for (int h = 1; h < NH; h++) sv = (u == h) ? s[h] : sv;
        es[t] = __expf(sv + cs[u]);             // es[g*8+u]
    }
    __syncthreads();

    // ---- block partial q[h][f] = sum_j e[j,h] x[j,f] (f-parallel, 4 j-lanes) ----
    {
        const int f = t & 63, l = t >> 6;
        float acc[NH];
        #pragma unroll
        for (int h = 0; h < NH; h++) acc[h] = 0.f;
        for (int jj = l; jj < RPB; jj += 4) {
            float xv = xs[jj * 65 + f];
            #pragma unroll
            for (int h = 0; h < NH; h++) acc[h] += es[jj * 8 + h] * xv;
        }
        #pragma unroll
        for (int h = 0; h < NH; h++) atomicAdd(&qs[h * 64 + f], acc[h]);
    }
    __syncthreads();

    // ---- publish via RED atomics (no return) ----
    for (int e = t; e < NH * 64; e += NT) atomicAdd(&g_q[e], qs[e]);
    if (t < NH) {
        float z = 0.f;
        #pragma unroll
        for (int jj = 0; jj < RPB; jj++) z += es[jj * 8 + t];
        atomicAdd(&g_Z[t], z);
    }
    __threadfence();
    __syncthreads();

    // ---- single grid sync: arrive + poll ----
    if (t == 0) {
        atomicAdd(&g_arrive, 1);
        while (*(volatile unsigned*)&g_arrive < NBLK) __nanosleep(32);
    }
    __syncthreads();
    __threadfence();

    // ---- redundant tail on every block (520-float read, ~34K MACs) ----
    if (t < NH) zs[t] = g_Z[t];
    __syncthreads();
    for (int e = t; e < NH * 64; e += NT) us[e] = g_q[e] / zs[e >> 6];
    __syncthreads();
    // v[h][f] = b1[f] + W1[f,:] . qn[h,:]   (reuse qs as vs)
    for (int e = t; e < NH * 64; e += NT) {
        int h = e >> 6, f = e & 63;
        float s = b1s[f];
        #pragma unroll 16
        for (int k = 0; k < 64; k++) s += W1s[f * 65 + k] * us[h * 64 + k];
        qs[e] = s;
    }
    __syncthreads();
    if (t < 64) {
        float m = 0.f;
        #pragma unroll
        for (int h = 0; h < NH; h++) m += qs[h * 64 + t];
        m *= (1.f / NH);
        float lr = m > 0.f ? m : 0.2f * m;
        os[t] = lr > 0.f ? lr : (__expf(lr) - 1.f);
    }
    __syncthreads();
    if (t < F_OUT) {
        float s = b2s[t];
        #pragma unroll 16
        for (int f = 0; f < 64; f++) s += W2s[t * 64 + f] * os[f];
        fs[t] = s > 0.f ? s : 0.2f * s;
    }
    __syncthreads();

    // ---- broadcast final row to this block's 32 output rows (float4) ----
    {
        int f0 = (t & 7) << 2;
        float4 v = make_float4(fs[f0], fs[f0 + 1], fs[f0 + 2], fs[f0 + 3]);
        ((float4*)out)[b * 256 + t] = v;
    }

    // ---- reset accumulators for next graph replay (last exiting block) ----
    __syncthreads();
    if (t == 0) s_last = (atomicAdd(&g_exit, 1) == NBLK - 1);
    __syncthreads();
    if (s_last) {
        for (int e = t; e < NH * 64; e += NT) g_q[e] = 0.f;
        if (t < NH) g_Z[t] = 0.f;
        if (t == 0) { g_arrive = 0; g_exit = 0; }
    }
}

extern "C" void kernel_launch(void* const* d_in, const int* in_sizes, int n_in,
                              void* d_out, int out_size) {
    const float* x   = (const float*)d_in[0];
    const float* W1  = (const float*)d_in[1];
    const float* b1  = (const float*)d_in[2];
    const float* a1w = (const float*)d_in[3];
    const float* a1b = (const float*)d_in[4];
    const float* W2  = (const float*)d_in[5];
    const float* b2  = (const float*)d_in[6];
    // d_in[7] (a2_w), d_in[8] (a2_b): provably no effect on output.

    gat_fused<<<NBLK, NT>>>(x, W1, b1, a1w, a1b, W2, b2, (float*)d_out);
}